// round 5
// baseline (speedup 1.0000x reference)
#include <cuda_runtime.h>
#include <cstdint>

// Problem-shape capacities (fixed by the dataset: N=100000, E=3200000)
#define NCAP 100000

// Static device scratch (allocation-free rule). float4-typed => 16B-aligned,
// so vector loads and RED.128 atomics on them are legal.
__device__ float  g_deg [NCAP];
__device__ float  g_dinv[NCAP];
__device__ float4 g_hs1 [NCAP * 8];   // (x@W1)*dinv[row]      (32 floats/row)
__device__ float4 g_acc1[NCAP * 8];   // edge agg, then z1 (post in-place)
__device__ float4 g_hs2 [NCAP * 4];   // (z1@W2)*dinv[row]     (16 floats/row)
__device__ float4 g_acc2[NCAP * 4];   // edge agg, then z2 (post in-place)

template <int LAYER> __device__ __forceinline__ float* hs_buf()  {
    return reinterpret_cast<float*>((LAYER == 1) ? g_hs1 : g_hs2);
}
template <int LAYER> __device__ __forceinline__ float* acc_buf() {
    return reinterpret_cast<float*>((LAYER == 1) ? g_acc1 : g_acc2);
}
template <int LAYER> __device__ __forceinline__ float4* hs4_buf()  {
    return (LAYER == 1) ? g_hs1 : g_hs2;
}
template <int LAYER> __device__ __forceinline__ float4* acc4_buf() {
    return (LAYER == 1) ? g_acc1 : g_acc2;
}

// ---------------------------------------------------------------------------
// init: deg=1 (self-loop weight), acc buffers = 0
__global__ void k_init(int N) {
    int i = blockIdx.x * blockDim.x + threadIdx.x;
    if (i < N) g_deg[i] = 1.0f;
    float4 z = make_float4(0.f, 0.f, 0.f, 0.f);
    if (i < N * 8) g_acc1[i] = z;
    if (i < N * 4) g_acc2[i] = z;
}

// degree accumulation over edges: deg[dst] += w
// edge_index is INT32 (JAX x64 disabled demotes int64 -> int32), layout [2,E].
__global__ void k_deg(const int* __restrict__ ei,
                      const float* __restrict__ ew, int E) {
    int e = blockIdx.x * blockDim.x + threadIdx.x;
    if (e >= E) return;
    int dst = __ldg(ei + E + e);
    atomicAdd(&g_deg[dst], __ldg(ew + e));
}

__global__ void k_dinv(int N) {
    int i = blockIdx.x * blockDim.x + threadIdx.x;
    if (i >= N) return;
    float d = g_deg[i];
    g_dinv[i] = (d > 0.0f) ? rsqrtf(d) : 0.0f;
}

// ---------------------------------------------------------------------------
// Row GEMM with dinv scaling epilogue: hs[row] = (X[row] @ W) * dinv[row]
template <int FIN, int FOUT, int LAYER>
__global__ void k_gemm_scale(const float* __restrict__ Xin,
                             const float* __restrict__ W, int N) {
    __shared__ float sW[FIN * FOUT];
    for (int i = threadIdx.x; i < FIN * FOUT; i += blockDim.x) sW[i] = W[i];
    __syncthreads();

    int row = blockIdx.x * blockDim.x + threadIdx.x;
    if (row >= N) return;

    const float* X = (LAYER == 1) ? Xin : acc_buf<1>();   // layer2 input = z1
    float* HS = hs_buf<LAYER>();

    float acc[FOUT];
#pragma unroll
    for (int j = 0; j < FOUT; j++) acc[j] = 0.0f;

    const float4* xr = reinterpret_cast<const float4*>(X + (size_t)row * FIN);
#pragma unroll
    for (int k4 = 0; k4 < FIN / 4; k4++) {
        float4 v = __ldg(xr + k4);
        const float* w0 = &sW[(k4 * 4 + 0) * FOUT];
        const float* w1 = &sW[(k4 * 4 + 1) * FOUT];
        const float* w2 = &sW[(k4 * 4 + 2) * FOUT];
        const float* w3 = &sW[(k4 * 4 + 3) * FOUT];
#pragma unroll
        for (int j = 0; j < FOUT; j++)
            acc[j] += v.x * w0[j] + v.y * w1[j] + v.z * w2[j] + v.w * w3[j];
    }

    float s = g_dinv[row];
    float* o = HS + (size_t)row * FOUT;
#pragma unroll
    for (int j = 0; j < FOUT; j++) o[j] = acc[j] * s;
}

// ---------------------------------------------------------------------------
// Edge aggregation: acc[dst] += w * hs[src], float4-vectorized RED.128.
// CH = FOUT/4 threads per edge, contiguous -> coalesced gather + red.
template <int FOUT, int LAYER>
__global__ void k_agg(const int* __restrict__ ei,
                      const float* __restrict__ ew, int E) {
    constexpr int CH = FOUT / 4;           // 8 (layer1) or 4 (layer2)
    long long tid = (long long)blockIdx.x * blockDim.x + threadIdx.x;
    int e = (int)(tid / CH);
    int c = (int)(tid % CH);
    if (e >= E) return;

    int   src = __ldg(ei + e);
    int   dst = __ldg(ei + E + e);
    float w   = __ldg(ew + e);

    float4 v = __ldg(hs4_buf<LAYER>() + (size_t)src * CH + c);
    v.x *= w; v.y *= w; v.z *= w; v.w *= w;

    atomicAdd(acc4_buf<LAYER>() + (size_t)dst * CH + c, v);
}

// ---------------------------------------------------------------------------
// Post: z = relu(dinv[row]*(acc + hs) + b), in place into acc (float4 lanes)
template <int FOUT, int LAYER>
__global__ void k_post(const float* __restrict__ b, int N) {
    constexpr int CH = FOUT / 4;
    int idx = blockIdx.x * blockDim.x + threadIdx.x;   // [N*CH)
    if (idx >= N * CH) return;
    int row = idx / CH;
    int c   = idx - row * CH;
    float4 a  = acc4_buf<LAYER>()[idx];
    float4 h  = hs4_buf<LAYER>()[idx];
    float  s  = g_dinv[row];
    float4 bb = __ldg(reinterpret_cast<const float4*>(b) + c);
    a.x = fmaxf(s * (a.x + h.x) + bb.x, 0.0f);
    a.y = fmaxf(s * (a.y + h.y) + bb.y, 0.0f);
    a.z = fmaxf(s * (a.z + h.z) + bb.z, 0.0f);
    a.w = fmaxf(s * (a.w + h.w) + bb.w, 0.0f);
    acc4_buf<LAYER>()[idx] = a;
}

// ---------------------------------------------------------------------------
// Final linear: out[row] = z2[row] @ Wout + bout   (16 -> 3)
__global__ void k_out(const float* __restrict__ Wout,
                      const float* __restrict__ bout,
                      float* __restrict__ out, int N) {
    __shared__ float sW[16 * 3];
    __shared__ float sb[3];
    if (threadIdx.x < 48) sW[threadIdx.x] = Wout[threadIdx.x];
    if (threadIdx.x < 3)  sb[threadIdx.x] = bout[threadIdx.x];
    __syncthreads();

    int row = blockIdx.x * blockDim.x + threadIdx.x;
    if (row >= N) return;

    float a0 = sb[0], a1 = sb[1], a2 = sb[2];
    const float* z = acc_buf<2>() + (size_t)row * 16;
#pragma unroll
    for (int k = 0; k < 16; k++) {
        float v = z[k];
        a0 += v * sW[k * 3 + 0];
        a1 += v * sW[k * 3 + 1];
        a2 += v * sW[k * 3 + 2];
    }
    float* o = out + (size_t)row * 3;
    o[0] = a0; o[1] = a1; o[2] = a2;
}

// ---------------------------------------------------------------------------
extern "C" void kernel_launch(void* const* d_in, const int* in_sizes, int n_in,
                              void* d_out, int out_size) {
    const float* x    = (const float*)d_in[0];
    const int*   ei   = (const int*)d_in[1];     // int32 [2, E] (JAX x64 off)
    const float* ew   = (const float*)d_in[2];
    const float* W1   = (const float*)d_in[3];
    const float* b1   = (const float*)d_in[4];
    const float* W2   = (const float*)d_in[5];
    const float* b2   = (const float*)d_in[6];
    const float* Wout = (const float*)d_in[7];
    const float* bout = (const float*)d_in[8];
    float*       out  = (float*)d_out;

    const int N = in_sizes[0] / 128;
    const int E = in_sizes[2];

    const int B = 256;
    auto blocks = [B](long long n) { return (unsigned)((n + B - 1) / B); };

    // 1. init scratch (deg=1 self-loop, acc=0)
    k_init<<<blocks((long long)N * 8), B>>>(N);
    // 2. degree + dinv
    k_deg<<<blocks(E), B>>>(ei, ew, E);
    k_dinv<<<blocks(N), B>>>(N);
    // 3. layer 1: hs1 = (x @ W1)*dinv ; agg ; post(relu) -> z1 in acc1
    k_gemm_scale<128, 32, 1><<<blocks(N), B>>>(x, W1, N);
    k_agg<32, 1><<<blocks((long long)E * 8), B>>>(ei, ew, E);
    k_post<32, 1><<<blocks((long long)N * 8), B>>>(b1, N);
    // 4. layer 2: hs2 = (z1 @ W2)*dinv ; agg ; post(relu) -> z2 in acc2
    k_gemm_scale<32, 16, 2><<<blocks(N), B>>>(nullptr, W2, N);
    k_agg<16, 2><<<blocks((long long)E * 4), B>>>(ei, ew, E);
    k_post<16, 2><<<blocks((long long)N * 4), B>>>(b2, N);
    // 5. output linear
    k_out<<<blocks(N), B>>>(Wout, bout, out, N);
}

// round 6
// speedup vs baseline: 1.0619x; 1.0619x over previous
#include <cuda_runtime.h>
#include <cstdint>

// Problem-shape capacities (fixed by the dataset: N=100000, E=3200000)
#define NCAP 100000

// Static device scratch (allocation-free rule). float4-typed => 16B-aligned,
// so vector loads and RED.128 atomics on them are legal.
__device__ float  g_deg [NCAP];
__device__ float  g_dinv[NCAP];
__device__ float4 g_hs1 [NCAP * 8];   // (x@W1)*dinv[row]      (32 floats/row)
__device__ float4 g_acc1[NCAP * 8];   // edge agg, then z1 (post in-place)
__device__ float4 g_hs2 [NCAP * 4];   // (z1@W2)*dinv[row]     (16 floats/row)
__device__ float4 g_acc2[NCAP * 4];   // edge agg, then z2 (post in-place)

template <int LAYER> __device__ __forceinline__ float* hs_buf()  {
    return reinterpret_cast<float*>((LAYER == 1) ? g_hs1 : g_hs2);
}
template <int LAYER> __device__ __forceinline__ float* acc_buf() {
    return reinterpret_cast<float*>((LAYER == 1) ? g_acc1 : g_acc2);
}
template <int LAYER> __device__ __forceinline__ float4* hs4_buf()  {
    return (LAYER == 1) ? g_hs1 : g_hs2;
}
template <int LAYER> __device__ __forceinline__ float4* acc4_buf() {
    return (LAYER == 1) ? g_acc1 : g_acc2;
}

// ---------------------------------------------------------------------------
// init: deg=1 (self-loop weight), acc buffers = 0
__global__ void k_init(int N) {
    int i = blockIdx.x * blockDim.x + threadIdx.x;
    if (i < N) g_deg[i] = 1.0f;
    float4 z = make_float4(0.f, 0.f, 0.f, 0.f);
    if (i < N * 8) g_acc1[i] = z;
    if (i < N * 4) g_acc2[i] = z;
}

// degree accumulation over edges: deg[dst] += w  (edge_index is int32 [2,E])
__global__ void k_deg(const int* __restrict__ ei,
                      const float* __restrict__ ew, int E) {
    int e = blockIdx.x * blockDim.x + threadIdx.x;
    if (e >= E) return;
    int dst = __ldg(ei + E + e);
    atomicAdd(&g_deg[dst], __ldg(ew + e));
}

__global__ void k_dinv(int N) {
    int i = blockIdx.x * blockDim.x + threadIdx.x;
    if (i >= N) return;
    float d = g_deg[i];
    g_dinv[i] = (d > 0.0f) ? rsqrtf(d) : 0.0f;
}

// ---------------------------------------------------------------------------
// Register-tiled GEMM with dinv epilogue: hs[row] = (X[row] @ W) * dinv[row]
// Thread micro-tile: TM=4 rows x 4 cols (16 accumulators).
// Per 4-k step: 4 LDG.128 (x, broadcast across NCT col-threads) +
//               4 LDS.128 (W) + 64 FMA  => FMA ~89% of issue.
template <int FIN, int FOUT, int LAYER>
__global__ void __launch_bounds__(32 * (FOUT / 4))
k_gemm_tiled(const float* __restrict__ Xin,
             const float* __restrict__ W, int N) {
    constexpr int NCT = FOUT / 4;       // col-threads: 8 (L1) or 4 (L2)
    constexpr int NRT = 32;             // row-thread groups
    constexpr int TM  = 4;              // rows per thread
    constexpr int BM  = NRT * TM;       // 128 rows per block
    constexpr int NT  = NCT * NRT;      // 256 or 128 threads

    __shared__ float sW[FIN * FOUT];
    for (int i = threadIdx.x; i < FIN * FOUT / 4; i += NT)
        reinterpret_cast<float4*>(sW)[i] =
            __ldg(reinterpret_cast<const float4*>(W) + i);
    __syncthreads();

    const float* X = (LAYER == 1) ? Xin : acc_buf<1>();
    const int ci = threadIdx.x % NCT;
    const int ri = threadIdx.x / NCT;
    const int r0 = blockIdx.x * BM + ri * TM;

    float acc[TM][4];
#pragma unroll
    for (int t = 0; t < TM; t++)
#pragma unroll
        for (int j = 0; j < 4; j++) acc[t][j] = 0.0f;

    const bool full = (r0 + TM <= N);

#pragma unroll 4
    for (int k4 = 0; k4 < FIN / 4; k4++) {
        float xr[TM][4];
#pragma unroll
        for (int t = 0; t < TM; t++) {
            float4 v = make_float4(0.f, 0.f, 0.f, 0.f);
            int r = r0 + t;
            if (full || r < N)
                v = __ldg(reinterpret_cast<const float4*>(X + (size_t)r * FIN) + k4);
            xr[t][0] = v.x; xr[t][1] = v.y; xr[t][2] = v.z; xr[t][3] = v.w;
        }
#pragma unroll
        for (int kk = 0; kk < 4; kk++) {
            float4 wv = *reinterpret_cast<const float4*>(
                &sW[(k4 * 4 + kk) * FOUT + ci * 4]);
#pragma unroll
            for (int t = 0; t < TM; t++) {
                float xs = xr[t][kk];
                acc[t][0] += xs * wv.x;
                acc[t][1] += xs * wv.y;
                acc[t][2] += xs * wv.z;
                acc[t][3] += xs * wv.w;
            }
        }
    }

    float4* HS = hs4_buf<LAYER>();
#pragma unroll
    for (int t = 0; t < TM; t++) {
        int r = r0 + t;
        if (r < N) {
            float s = g_dinv[r];
            float4 o = make_float4(acc[t][0] * s, acc[t][1] * s,
                                   acc[t][2] * s, acc[t][3] * s);
            HS[(size_t)r * NCT + ci] = o;
        }
    }
}

// ---------------------------------------------------------------------------
// Edge aggregation: acc[dst] += w * hs[src], float4-vectorized RED.128.
// CH = FOUT/4 threads per edge, contiguous -> coalesced gather + red.
template <int FOUT, int LAYER>
__global__ void k_agg(const int* __restrict__ ei,
                      const float* __restrict__ ew, int E) {
    constexpr int CH = FOUT / 4;           // 8 (layer1) or 4 (layer2)
    long long tid = (long long)blockIdx.x * blockDim.x + threadIdx.x;
    int e = (int)(tid / CH);
    int c = (int)(tid % CH);
    if (e >= E) return;

    int   src = __ldg(ei + e);
    int   dst = __ldg(ei + E + e);
    float w   = __ldg(ew + e);

    float4 v = __ldg(hs4_buf<LAYER>() + (size_t)src * CH + c);
    v.x *= w; v.y *= w; v.z *= w; v.w *= w;

    atomicAdd(acc4_buf<LAYER>() + (size_t)dst * CH + c, v);
}

// ---------------------------------------------------------------------------
// Post: z = relu(dinv[row]*(acc + hs) + b), in place into acc (float4 lanes)
template <int FOUT, int LAYER>
__global__ void k_post(const float* __restrict__ b, int N) {
    constexpr int CH = FOUT / 4;
    int idx = blockIdx.x * blockDim.x + threadIdx.x;   // [N*CH)
    if (idx >= N * CH) return;
    int row = idx / CH;
    int c   = idx - row * CH;
    float4 a  = acc4_buf<LAYER>()[idx];
    float4 h  = hs4_buf<LAYER>()[idx];
    float  s  = g_dinv[row];
    float4 bb = __ldg(reinterpret_cast<const float4*>(b) + c);
    a.x = fmaxf(s * (a.x + h.x) + bb.x, 0.0f);
    a.y = fmaxf(s * (a.y + h.y) + bb.y, 0.0f);
    a.z = fmaxf(s * (a.z + h.z) + bb.z, 0.0f);
    a.w = fmaxf(s * (a.w + h.w) + bb.w, 0.0f);
    acc4_buf<LAYER>()[idx] = a;
}

// ---------------------------------------------------------------------------
// Final linear: out[row] = z2[row] @ Wout + bout   (16 -> 3)
__global__ void k_out(const float* __restrict__ Wout,
                      const float* __restrict__ bout,
                      float* __restrict__ out, int N) {
    __shared__ float sW[16 * 3];
    __shared__ float sb[3];
    if (threadIdx.x < 48) sW[threadIdx.x] = Wout[threadIdx.x];
    if (threadIdx.x < 3)  sb[threadIdx.x] = bout[threadIdx.x];
    __syncthreads();

    int row = blockIdx.x * blockDim.x + threadIdx.x;
    if (row >= N) return;

    float a0 = sb[0], a1 = sb[1], a2 = sb[2];
    const float* z = acc_buf<2>() + (size_t)row * 16;
#pragma unroll
    for (int k = 0; k < 16; k++) {
        float v = z[k];
        a0 += v * sW[k * 3 + 0];
        a1 += v * sW[k * 3 + 1];
        a2 += v * sW[k * 3 + 2];
    }
    float* o = out + (size_t)row * 3;
    o[0] = a0; o[1] = a1; o[2] = a2;
}

// ---------------------------------------------------------------------------
extern "C" void kernel_launch(void* const* d_in, const int* in_sizes, int n_in,
                              void* d_out, int out_size) {
    const float* x    = (const float*)d_in[0];
    const int*   ei   = (const int*)d_in[1];     // int32 [2, E] (JAX x64 off)
    const float* ew   = (const float*)d_in[2];
    const float* W1   = (const float*)d_in[3];
    const float* b1   = (const float*)d_in[4];
    const float* W2   = (const float*)d_in[5];
    const float* b2   = (const float*)d_in[6];
    const float* Wout = (const float*)d_in[7];
    const float* bout = (const float*)d_in[8];
    float*       out  = (float*)d_out;

    const int N = in_sizes[0] / 128;
    const int E = in_sizes[2];

    const int B = 256;
    auto blocks = [B](long long n) { return (unsigned)((n + B - 1) / B); };
    const unsigned gemm_grid = (unsigned)((N + 127) / 128);   // BM = 128

    // 1. init scratch (deg=1 self-loop, acc=0)
    k_init<<<blocks((long long)N * 8), B>>>(N);
    // 2. degree + dinv
    k_deg<<<blocks(E), B>>>(ei, ew, E);
    k_dinv<<<blocks(N), B>>>(N);
    // 3. layer 1: hs1 = (x @ W1)*dinv ; agg ; post(relu) -> z1 in acc1
    k_gemm_tiled<128, 32, 1><<<gemm_grid, 256>>>(x, W1, N);
    k_agg<32, 1><<<blocks((long long)E * 8), B>>>(ei, ew, E);
    k_post<32, 1><<<blocks((long long)N * 8), B>>>(b1, N);
    // 4. layer 2: hs2 = (z1 @ W2)*dinv ; agg ; post(relu) -> z2 in acc2
    k_gemm_tiled<32, 16, 2><<<gemm_grid, 128>>>(nullptr, W2, N);
    k_agg<16, 2><<<blocks((long long)E * 4), B>>>(ei, ew, E);
    k_post<16, 2><<<blocks((long long)N * 4), B>>>(b2, N);
    // 5. output linear
    k_out<<<blocks(N), B>>>(Wout, bout, out, N);
}

// round 7
// speedup vs baseline: 1.0918x; 1.0282x over previous
#include <cuda_runtime.h>
#include <cstdint>

// Problem-shape capacities (fixed by the dataset: N=100000, E=3200000)
#define NCAP 100000

// Static device scratch. float4-typed => 16B-aligned => LDG.128/RED.128 legal.
__device__ float  g_deg [NCAP];
__device__ float  g_dinv[NCAP];
__device__ float4 g_hs1 [NCAP * 8];   // (x@W1)*dinv[row]      (32 floats/row)
__device__ float4 g_acc1[NCAP * 8];   // edge agg for layer 1
__device__ float4 g_hs2 [NCAP * 4];   // (z1@W2)*dinv[row]     (16 floats/row)
__device__ float4 g_acc2[NCAP * 4];   // edge agg for layer 2

template <int LAYER> __device__ __forceinline__ float4* hs4_buf()  {
    return (LAYER == 1) ? g_hs1 : g_hs2;
}
template <int LAYER> __device__ __forceinline__ float4* acc4_buf() {
    return (LAYER == 1) ? g_acc1 : g_acc2;
}

// ---------------------------------------------------------------------------
// init: deg=1 (self-loop weight), acc buffers = 0
__global__ void k_init(int N) {
    int i = blockIdx.x * blockDim.x + threadIdx.x;
    if (i < N) g_deg[i] = 1.0f;
    float4 z = make_float4(0.f, 0.f, 0.f, 0.f);
    if (i < N * 8) g_acc1[i] = z;
    if (i < N * 4) g_acc2[i] = z;
}

// degree accumulation over edges: deg[dst] += w  (edge_index is int32 [2,E])
__global__ void k_deg(const int* __restrict__ ei,
                      const float* __restrict__ ew, int E) {
    int e = blockIdx.x * blockDim.x + threadIdx.x;
    if (e >= E) return;
    int dst = __ldg(ei + E + e);
    atomicAdd(&g_deg[dst], __ldg(ew + e));
}

__global__ void k_dinv(int N) {
    int i = blockIdx.x * blockDim.x + threadIdx.x;
    if (i >= N) return;
    float d = g_deg[i];
    g_dinv[i] = (d > 0.0f) ? rsqrtf(d) : 0.0f;
}

// ---------------------------------------------------------------------------
// Register-tiled GEMM, TM=8 rows x 4 cols per thread, BM=256 rows/block.
// LAYER==1: X = raw input x.
// LAYER==2: X row k4-chunk reconstructed inline as
//           relu(dinv[r]*(acc1+hs1)+b1)  (fused post1).
// Epilogue: hs<LAYER>[row] = (X[row] @ W) * dinv[row].
template <int FIN, int FOUT, int LAYER>
__global__ void __launch_bounds__(32 * (FOUT / 4))
k_gemm_tiled(const float* __restrict__ Xin,
             const float* __restrict__ W,
             const float* __restrict__ bprev, int N) {
    constexpr int NCT = FOUT / 4;       // col-threads: 8 (L1) or 4 (L2)
    constexpr int TM  = 8;              // rows per thread
    constexpr int BM  = 32 * TM;        // 256 rows per block
    constexpr int NT  = NCT * 32;       // 256 or 128 threads

    __shared__ float sW[FIN * FOUT];
    __shared__ float4 sB[FIN / 4];      // b1 (layer2 fusion); unused layer1
    for (int i = threadIdx.x; i < FIN * FOUT / 4; i += NT)
        reinterpret_cast<float4*>(sW)[i] =
            __ldg(reinterpret_cast<const float4*>(W) + i);
    if (LAYER == 2 && threadIdx.x < FIN / 4)
        sB[threadIdx.x] = __ldg(reinterpret_cast<const float4*>(bprev) + threadIdx.x);
    __syncthreads();

    const int ci = threadIdx.x % NCT;
    const int ri = threadIdx.x / NCT;
    const int r0 = blockIdx.x * BM + ri * TM;
    const bool full = (r0 + TM <= N);

    float acc[TM][4];
#pragma unroll
    for (int t = 0; t < TM; t++)
#pragma unroll
        for (int j = 0; j < 4; j++) acc[t][j] = 0.0f;

    float srow[TM];   // dinv per row (needed for layer2 fused input + epilogue)
#pragma unroll
    for (int t = 0; t < TM; t++) {
        int r = r0 + t;
        srow[t] = (full || r < N) ? g_dinv[r] : 0.0f;
    }

#pragma unroll
    for (int k4 = 0; k4 < FIN / 4; k4++) {
        float xr[TM][4];
#pragma unroll
        for (int t = 0; t < TM; t++) {
            int r = r0 + t;
            float4 v = make_float4(0.f, 0.f, 0.f, 0.f);
            if (full || r < N) {
                if (LAYER == 1) {
                    v = __ldg(reinterpret_cast<const float4*>(Xin + (size_t)r * FIN) + k4);
                } else {
                    // fused post1: z1 = relu(dinv*(acc1+hs1)+b1)
                    float4 a = __ldg(g_acc1 + (size_t)r * (FIN / 4) + k4);
                    float4 h = __ldg(g_hs1  + (size_t)r * (FIN / 4) + k4);
                    float4 bb = sB[k4];
                    float  s = srow[t];
                    v.x = fmaxf(s * (a.x + h.x) + bb.x, 0.0f);
                    v.y = fmaxf(s * (a.y + h.y) + bb.y, 0.0f);
                    v.z = fmaxf(s * (a.z + h.z) + bb.z, 0.0f);
                    v.w = fmaxf(s * (a.w + h.w) + bb.w, 0.0f);
                }
            }
            xr[t][0] = v.x; xr[t][1] = v.y; xr[t][2] = v.z; xr[t][3] = v.w;
        }
#pragma unroll
        for (int kk = 0; kk < 4; kk++) {
            float4 wv = *reinterpret_cast<const float4*>(
                &sW[(k4 * 4 + kk) * FOUT + ci * 4]);
#pragma unroll
            for (int t = 0; t < TM; t++) {
                float xs = xr[t][kk];
                acc[t][0] += xs * wv.x;
                acc[t][1] += xs * wv.y;
                acc[t][2] += xs * wv.z;
                acc[t][3] += xs * wv.w;
            }
        }
    }

    float4* HS = hs4_buf<LAYER>();
#pragma unroll
    for (int t = 0; t < TM; t++) {
        int r = r0 + t;
        if (full || r < N) {
            float s = srow[t];
            HS[(size_t)r * NCT + ci] = make_float4(acc[t][0] * s, acc[t][1] * s,
                                                   acc[t][2] * s, acc[t][3] * s);
        }
    }
}

// ---------------------------------------------------------------------------
// Edge aggregation: acc[dst] += w * hs[src], float4-vectorized RED.128.
// CH = FOUT/4 threads per edge, contiguous -> coalesced gather + red.
template <int FOUT, int LAYER>
__global__ void k_agg(const int* __restrict__ ei,
                      const float* __restrict__ ew, int E) {
    constexpr int CH = FOUT / 4;           // 8 (layer1) or 4 (layer2)
    long long tid = (long long)blockIdx.x * blockDim.x + threadIdx.x;
    int e = (int)(tid / CH);
    int c = (int)(tid % CH);
    if (e >= E) return;

    int   src = __ldg(ei + e);
    int   dst = __ldg(ei + E + e);
    float w   = __ldg(ew + e);

    float4 v = __ldg(hs4_buf<LAYER>() + (size_t)src * CH + c);
    v.x *= w; v.y *= w; v.z *= w; v.w *= w;

    atomicAdd(acc4_buf<LAYER>() + (size_t)dst * CH + c, v);
}

// ---------------------------------------------------------------------------
// Final linear fused with post2: z2 = relu(dinv*(acc2+hs2)+b2);
// out[row] = z2 @ Wout + bout   (16 -> 3)
__global__ void k_out(const float* __restrict__ b2,
                      const float* __restrict__ Wout,
                      const float* __restrict__ bout,
                      float* __restrict__ out, int N) {
    __shared__ float  sW[16 * 3];
    __shared__ float  sb[3];
    __shared__ float4 sB2[4];
    if (threadIdx.x < 48) sW[threadIdx.x] = Wout[threadIdx.x];
    if (threadIdx.x < 3)  sb[threadIdx.x] = bout[threadIdx.x];
    if (threadIdx.x < 4)
        sB2[threadIdx.x] = __ldg(reinterpret_cast<const float4*>(b2) + threadIdx.x);
    __syncthreads();

    int row = blockIdx.x * blockDim.x + threadIdx.x;
    if (row >= N) return;

    float s = g_dinv[row];
    float a0 = sb[0], a1 = sb[1], a2 = sb[2];
#pragma unroll
    for (int c = 0; c < 4; c++) {
        float4 a = __ldg(g_acc2 + (size_t)row * 4 + c);
        float4 h = __ldg(g_hs2  + (size_t)row * 4 + c);
        float4 bb = sB2[c];
        float z[4];
        z[0] = fmaxf(s * (a.x + h.x) + bb.x, 0.0f);
        z[1] = fmaxf(s * (a.y + h.y) + bb.y, 0.0f);
        z[2] = fmaxf(s * (a.z + h.z) + bb.z, 0.0f);
        z[3] = fmaxf(s * (a.w + h.w) + bb.w, 0.0f);
#pragma unroll
        for (int q = 0; q < 4; q++) {
            int k = c * 4 + q;
            a0 += z[q] * sW[k * 3 + 0];
            a1 += z[q] * sW[k * 3 + 1];
            a2 += z[q] * sW[k * 3 + 2];
        }
    }
    float* o = out + (size_t)row * 3;
    o[0] = a0; o[1] = a1; o[2] = a2;
}

// ---------------------------------------------------------------------------
extern "C" void kernel_launch(void* const* d_in, const int* in_sizes, int n_in,
                              void* d_out, int out_size) {
    const float* x    = (const float*)d_in[0];
    const int*   ei   = (const int*)d_in[1];     // int32 [2, E] (JAX x64 off)
    const float* ew   = (const float*)d_in[2];
    const float* W1   = (const float*)d_in[3];
    const float* b1   = (const float*)d_in[4];
    const float* W2   = (const float*)d_in[5];
    const float* b2   = (const float*)d_in[6];
    const float* Wout = (const float*)d_in[7];
    const float* bout = (const float*)d_in[8];
    float*       out  = (float*)d_out;

    const int N = in_sizes[0] / 128;
    const int E = in_sizes[2];

    const int B = 256;
    auto blocks = [B](long long n) { return (unsigned)((n + B - 1) / B); };
    const unsigned gemm_grid = (unsigned)((N + 255) / 256);   // BM = 256

    // 1. init scratch (deg=1 self-loop, acc=0), degree + dinv
    k_init<<<blocks((long long)N * 8), B>>>(N);
    k_deg<<<blocks(E), B>>>(ei, ew, E);
    k_dinv<<<blocks(N), B>>>(N);
    // 2. layer 1: hs1 = (x @ W1)*dinv ; agg
    k_gemm_tiled<128, 32, 1><<<gemm_grid, 256>>>(x, W1, nullptr, N);
    k_agg<32, 1><<<blocks((long long)E * 8), B>>>(ei, ew, E);
    // 3. layer 2 (fused post1): hs2 = (relu(dinv*(acc1+hs1)+b1) @ W2)*dinv ; agg
    k_gemm_tiled<32, 16, 2><<<gemm_grid, 128>>>(nullptr, W2, b1, N);
    k_agg<16, 2><<<blocks((long long)E * 4), B>>>(ei, ew, E);
    // 4. output linear (fused post2)
    k_out<<<blocks(N), B>>>(b2, Wout, bout, out, N);
}